// round 4
// baseline (speedup 1.0000x reference)
#include <cuda_runtime.h>
#include <math_constants.h>
#include <cfloat>

// Problem constants (B=2, L=256, A=12, C=32, K=30)
#define NB 2
#define NL 256
#define NA 12
#define NATOM 3072          // NL*NA
#define NC 32
#define KNB 30
#define BIGD 1000000.0f
#define MASKED_KEY 3.402823466e+38f  // FLT_MAX sentinel for masked candidates

// Output layout (all float32, concatenated in reference tuple order)
#define O_COORDS 0                       // (B, NATOM, 3)  -> 18432
#define O_MASK   (NB*NATOM*3)            // (B, NATOM)     -> 6144
#define O_ENC    (O_MASK + NB*NATOM)     // (B, NATOM, 32) -> 196608
#define O_DIST   (O_ENC + NB*NATOM*NC)   // (B, NATOM, 30) -> 184320
#define O_IDX    (O_DIST + NB*NATOM*KNB) // (B, NATOM, 30) -> 184320

#define ROWS 12              // rows (queries) per block
#define THREADS (ROWS * 32)  // 384
#define CPAD 97              // per-column padded stride in float4 (conflict-free)
#define NT 96                // candidates per lane/column (3072/32)

// Column-major atom store: s_T[(j&31)*CPAD + (j>>5)] = {x,y,z,mask}
//  - phase A (lane scans own column):  conflict-free (stride 97*16B, odd)
//  - rescan  (all lanes read column w): contiguous 16B/lane, conflict-free

__global__ void __launch_bounds__(THREADS, 4)
fused_kernel(const float* __restrict__ coords,
             const int* __restrict__ mask,
             const float* __restrict__ T,
             const float* __restrict__ scale,
             const float* __restrict__ shift,
             float* __restrict__ out) {
    extern __shared__ float4 s_T[];                  // 32*97 float4 = 49664 B
    __shared__ float s_red[8];

    int tid  = threadIdx.x;
    int warp = tid >> 5;
    int lane = tid & 31;

    int rowBase = blockIdx.x * ROWS;
    int b       = rowBase / NATOM;                   // blocks never straddle batches
    int ibBase  = rowBase - b * NATOM;
    const float* cb = coords + b * NATOM * 3;
    const int*   mb = mask + b * NL;

    // ---- cooperative load of this batch's atoms into column-major layout ----
    for (int a = tid; a < NATOM; a += THREADS) {
        float4 v;
        v.x = cb[a * 3 + 0];
        v.y = cb[a * 3 + 1];
        v.z = cb[a * 3 + 2];
        v.w = (float)mb[a / NA];
        s_T[(a & 31) * CPAD + (a >> 5)] = v;
    }

    // ---- nm = sum(mask[b]) : warps 0..7 reduce 32 masks each ----
    if (tid < NL) {
        int s = __reduce_add_sync(0xffffffffu, mb[tid]);
        if (lane == 0) s_red[warp] = (float)s;
    }
    __syncthreads();

    float nm = 0.f;
    #pragma unroll
    for (int i = 0; i < 8; ++i) nm += s_red[i];

    // ---- per-(b,c) graph-norm affine coefficients (closed form) ----
    int c = lane;
    float tv[NA];
    float colsum = 0.f;
    #pragma unroll
    for (int a = 0; a < NA; ++a) { tv[a] = T[a * NC + c]; colsum += tv[a]; }

    float cntA = nm * (float)NA;
    float cnt  = fmaxf(cntA, 1.0f);
    float mean = (nm * colsum) / cnt;

    float ssqm = 0.f;
    #pragma unroll
    for (int a = 0; a < NA; ++a) {
        float d = tv[a] - mean;
        ssqm = fmaf(d, d, ssqm);
    }
    float ssq  = nm * ssqm + ((float)NATOM - cntA) * mean * mean;
    float rstd = rsqrtf(ssq / cnt + 1e-5f);
    float Ac   = rstd * scale[c];
    float Bc   = shift[c] - mean * Ac;

    // ---- small outputs ----
    int row = rowBase + warp;
    int ib  = ibBase + warp;
    float4 q = s_T[(ib & 31) * CPAD + (ib >> 5)];

    {
        int ty = ib % NA;
        float v = (q.w != 0.0f) ? fmaf(tv[ty], Ac, Bc) : 0.0f;
        out[O_ENC + row * NC + c] = v;
    }
    if (tid < ROWS * 3) out[O_COORDS + rowBase * 3 + tid] = coords[rowBase * 3 + tid];
    if (tid < ROWS)     out[O_MASK + rowBase + tid] =
                            s_T[((ibBase + tid) & 31) * CPAD + ((ibBase + tid) >> 5)].w;

    float* dist_out = out + O_DIST + row * KNB;
    float* idx_out  = out + O_IDX  + row * KNB;

    if (q.w == 0.0f) {                        // masked row -> pad outputs
        if (lane < KNB) {
            dist_out[lane] = BIGD;
            idx_out[lane]  = 0.0f;
        }
        return;
    }

    // ---- phase A: per-lane scan of own column, running (min,idx) in bits ----
    const float4* myCol = s_T + lane * CPAD;
    unsigned bvb = 0xFFFFFFFFu;
    int bj = 0;
    #pragma unroll 4
    for (int t = 0; t < NT; ++t) {
        float4 a = myCol[t];
        float dx = q.x - a.x, dy = q.y - a.y, dz = q.z - a.z;
        float d2 = fmaf(dx, dx, fmaf(dy, dy, dz * dz));
        float key = (a.w == 0.0f) ? MASKED_KEY : d2;
        unsigned kb = __float_as_uint(key);   // d2 >= 0 -> bits order-preserving
        if (kb < bvb) { bvb = kb; bj = t * 32 + lane; }  // t asc -> lowest j on ties
    }

    // ---- extract-min x30; exclusion mask lives in lane-w's registers ----
    unsigned m0 = 0, m1 = 0, m2 = 0;          // extracted bits of my column
    unsigned rvb = 0; int rj = 0;             // lane p holds pass-p result
    #pragma unroll 1
    for (int p = 0; p < KNB; ++p) {
        unsigned mvb = __reduce_min_sync(0xffffffffu, bvb);
        unsigned cj  = (bvb == mvb) ? (unsigned)bj : 0xFFFFFFFFu;
        unsigned mj  = __reduce_min_sync(0xffffffffu, cj);
        if (lane == p) { rvb = mvb; rj = (int)mj; }

        if (p < KNB - 1) {
            int w  = (int)(mj & 31u);
            int tm = (int)(mj >> 5);
            int tw = tm >> 5;                 // which mask word
            unsigned bit = 1u << (tm & 31);
            bool own = (lane == w);
            if (own && tw == 0) m0 |= bit;
            if (own && tw == 1) m1 |= bit;
            if (own && tw == 2) m2 |= bit;
            unsigned w0 = __shfl_sync(0xffffffffu, m0, w);
            unsigned w1 = __shfl_sync(0xffffffffu, m1, w);
            unsigned w2 = __shfl_sync(0xffffffffu, m2, w);

            // cooperative rescan of column w (recompute keys, apply exclusions)
            const float4* col = s_T + w * CPAD;
            unsigned nvb = 0xFFFFFFFFu;
            int nj = 0;
            unsigned ex0 = (w0 >> lane) & 1u;
            unsigned ex1 = (w1 >> lane) & 1u;
            unsigned ex2 = (w2 >> lane) & 1u;
            #pragma unroll
            for (int s = 0; s < 3; ++s) {
                int t = lane + s * 32;
                float4 a = col[t];
                float dx = q.x - a.x, dy = q.y - a.y, dz = q.z - a.z;
                float d2 = fmaf(dx, dx, fmaf(dy, dy, dz * dz));
                float key = (a.w == 0.0f) ? MASKED_KEY : d2;
                unsigned kb = __float_as_uint(key);
                unsigned ex = (s == 0) ? ex0 : (s == 1) ? ex1 : ex2;
                kb = ex ? 0xFFFFFFFFu : kb;
                if (kb < nvb) { nvb = kb; nj = t * 32 + w; }
            }
            unsigned nmin = __reduce_min_sync(0xffffffffu, nvb);
            unsigned ncj  = (nvb == nmin) ? (unsigned)nj : 0xFFFFFFFFu;
            unsigned nidx = __reduce_min_sync(0xffffffffu, ncj);
            if (lane == w) { bvb = nmin; bj = (int)nidx; }
        }
    }

    if (lane < KNB) {
        float dv = (rvb == __float_as_uint(MASKED_KEY))
                       ? BIGD
                       : sqrtf(__uint_as_float(rvb) + 1e-6f);
        dist_out[lane] = dv;
        idx_out[lane]  = (float)rj;
    }
}

// ---------------------------------------------------------------------------
extern "C" void kernel_launch(void* const* d_in, const int* in_sizes, int n_in,
                              void* d_out, int out_size) {
    const float* coords = (const float*)d_in[0];   // (2,256,12,3) f32
    const int*   mask   = (const int*)d_in[1];     // (2,256) i32
    const float* emb    = (const float*)d_in[2];   // (12,32) f32
    const float* scale  = (const float*)d_in[3];   // (1,1,32) f32
    const float* shift  = (const float*)d_in[4];   // (1,1,32) f32
    float* out = (float*)d_out;

    int smem_bytes = 32 * CPAD * 16;               // 49664 B
    cudaFuncSetAttribute(fused_kernel, cudaFuncAttributeMaxDynamicSharedMemorySize,
                         smem_bytes);
    int nblocks = (NB * NATOM) / ROWS;             // 512
    fused_kernel<<<nblocks, THREADS, smem_bytes>>>(coords, mask, emb, scale, shift, out);
}

// round 5
// speedup vs baseline: 1.0649x; 1.0649x over previous
#include <cuda_runtime.h>
#include <math_constants.h>
#include <cfloat>

// Problem constants (B=2, L=256, A=12, C=32, K=30)
#define NB 2
#define NL 256
#define NA 12
#define NATOM 3072          // NL*NA
#define NC 32
#define KNB 30
#define BIGD 1000000.0f
#define MASKED_KEY 3.402823466e+38f  // FLT_MAX sentinel for masked candidates
#define MK_BITS 0x7F7FFFFFu          // bits of FLT_MAX
#define EMPTY_BITS 0xFFFFFFFFu       // list-slot / exclusion sentinel (> MK_BITS)

// Output layout (all float32, concatenated in reference tuple order)
#define O_COORDS 0                       // (B, NATOM, 3)  -> 18432
#define O_MASK   (NB*NATOM*3)            // (B, NATOM)     -> 6144
#define O_ENC    (O_MASK + NB*NATOM)     // (B, NATOM, 32) -> 196608
#define O_DIST   (O_ENC + NB*NATOM*NC)   // (B, NATOM, 30) -> 184320
#define O_IDX    (O_DIST + NB*NATOM*KNB) // (B, NATOM, 30) -> 184320

#define ROWS 12              // rows (queries) per block
#define THREADS (ROWS * 32)  // 384
#define CPAD 97              // per-column padded stride in float4 (conflict-free)
#define NT 96                // candidates per lane/column (3072/32)

// Column-major atom store: s_T[(j&31)*CPAD + (j>>5)] = {x,y,z,mask}

__global__ void __launch_bounds__(THREADS, 4)
fused_kernel(const float* __restrict__ coords,
             const int* __restrict__ mask,
             const float* __restrict__ T,
             const float* __restrict__ scale,
             const float* __restrict__ shift,
             float* __restrict__ out) {
    extern __shared__ float4 s_T[];                  // 32*97 float4 = 49664 B
    __shared__ float s_red[8];

    int tid  = threadIdx.x;
    int warp = tid >> 5;
    int lane = tid & 31;

    int rowBase = blockIdx.x * ROWS;
    int b       = rowBase / NATOM;                   // blocks never straddle batches
    int ibBase  = rowBase - b * NATOM;
    const float* cb = coords + b * NATOM * 3;
    const int*   mb = mask + b * NL;

    // ---- cooperative load of this batch's atoms into column-major layout ----
    for (int a = tid; a < NATOM; a += THREADS) {
        float4 v;
        v.x = cb[a * 3 + 0];
        v.y = cb[a * 3 + 1];
        v.z = cb[a * 3 + 2];
        v.w = (float)mb[a / NA];
        s_T[(a & 31) * CPAD + (a >> 5)] = v;
    }

    // ---- nm = sum(mask[b]) : warps 0..7 reduce 32 masks each ----
    if (tid < NL) {
        int s = __reduce_add_sync(0xffffffffu, mb[tid]);
        if (lane == 0) s_red[warp] = (float)s;
    }
    __syncthreads();

    float nm = 0.f;
    #pragma unroll
    for (int i = 0; i < 8; ++i) nm += s_red[i];

    // ---- per-(b,c) graph-norm affine coefficients (closed form) ----
    int c = lane;
    float tv[NA];
    float colsum = 0.f;
    #pragma unroll
    for (int a = 0; a < NA; ++a) { tv[a] = T[a * NC + c]; colsum += tv[a]; }

    float cntA = nm * (float)NA;
    float cnt  = fmaxf(cntA, 1.0f);
    float mean = (nm * colsum) / cnt;

    float ssqm = 0.f;
    #pragma unroll
    for (int a = 0; a < NA; ++a) {
        float d = tv[a] - mean;
        ssqm = fmaf(d, d, ssqm);
    }
    float ssq  = nm * ssqm + ((float)NATOM - cntA) * mean * mean;
    float rstd = rsqrtf(ssq / cnt + 1e-5f);
    float Ac   = rstd * scale[c];
    float Bc   = shift[c] - mean * Ac;

    // ---- small outputs ----
    int row = rowBase + warp;
    int ib  = ibBase + warp;
    float4 q = s_T[(ib & 31) * CPAD + (ib >> 5)];

    {
        int ty = ib % NA;
        float v = (q.w != 0.0f) ? fmaf(tv[ty], Ac, Bc) : 0.0f;
        out[O_ENC + row * NC + c] = v;
    }
    if (tid < ROWS * 3) out[O_COORDS + rowBase * 3 + tid] = coords[rowBase * 3 + tid];
    if (tid < ROWS)     out[O_MASK + rowBase + tid] =
                            s_T[((ibBase + tid) & 31) * CPAD + ((ibBase + tid) >> 5)].w;

    float* dist_out = out + O_DIST + row * KNB;
    float* idx_out  = out + O_IDX  + row * KNB;

    if (q.w == 0.0f) {                        // masked row -> pad outputs
        if (lane < KNB) {
            dist_out[lane] = BIGD;
            idx_out[lane]  = 0.0f;
        }
        return;
    }

    // ---- phase A: per-lane top-3 (key,idx) sorted list, registers only ----
    const float4* myCol = s_T + lane * CPAD;
    unsigned v0 = EMPTY_BITS, v1 = EMPTY_BITS, v2 = EMPTY_BITS;
    int i0 = 0, i1 = 0, i2 = 0;
    #pragma unroll 4
    for (int t = 0; t < NT; ++t) {
        float4 a = myCol[t];
        float dx = q.x - a.x, dy = q.y - a.y, dz = q.z - a.z;
        float d2 = fmaf(dx, dx, fmaf(dy, dy, dz * dz));
        float key = (a.w == 0.0f) ? MASKED_KEY : d2;
        unsigned kb = __float_as_uint(key);   // d2 >= 0 -> bits order-preserving
        int j = t * 32 + lane;
        if (kb < v2) {                        // strict < keeps lowest-index tie order
            if (kb < v1) {
                v2 = v1; i2 = i1;
                if (kb < v0) { v1 = v0; i1 = i0; v0 = kb; i0 = j; }
                else         { v1 = kb; i1 = j; }
            } else { v2 = kb; i2 = j; }
        }
    }

    // ---- extract-min x30 from the 32 lane-heads ----
    unsigned m0 = 0, m1 = 0, m2 = 0;          // exclusion bits of my column
    int cnt3 = 3;                             // valid entries remaining in my list
    unsigned rvb = 0; int rj = 0;             // lane p holds pass-p result
    #pragma unroll 1
    for (int p = 0; p < KNB; ++p) {
        unsigned mvb = __reduce_min_sync(0xffffffffu, v0);
        unsigned cj  = (v0 == mvb) ? (unsigned)i0 : 0xFFFFFFFFu;
        unsigned mj  = __reduce_min_sync(0xffffffffu, cj);
        if (lane == p) { rvb = mvb; rj = (int)mj; }

        if (p < KNB - 1) {
            int w = (int)(mj & 31u);
            // owner pops its head + records exclusion bit
            if (lane == w) {
                int tm = (int)(mj >> 5);
                int tw = tm >> 5;
                unsigned bit = 1u << (tm & 31);
                if (tw == 0) m0 |= bit; else if (tw == 1) m1 |= bit; else m2 |= bit;
                v0 = v1; i0 = i1; v1 = v2; i1 = i2; v2 = EMPTY_BITS;
                --cnt3;
            }
            bool empty = (lane == w) && (cnt3 == 0);
            if (__ballot_sync(0xffffffffu, empty)) {
                // rare: refill owner's head via cooperative rescan of column w
                unsigned w0 = __shfl_sync(0xffffffffu, m0, w);
                unsigned w1 = __shfl_sync(0xffffffffu, m1, w);
                unsigned w2 = __shfl_sync(0xffffffffu, m2, w);
                const float4* col = s_T + w * CPAD;
                unsigned nvb = EMPTY_BITS;
                int nj = 0;
                #pragma unroll
                for (int s = 0; s < 3; ++s) {
                    int t = lane + s * 32;
                    float4 a = col[t];
                    float dx = q.x - a.x, dy = q.y - a.y, dz = q.z - a.z;
                    float d2 = fmaf(dx, dx, fmaf(dy, dy, dz * dz));
                    float key = (a.w == 0.0f) ? MASKED_KEY : d2;
                    unsigned kb = __float_as_uint(key);
                    unsigned ex = ((s == 0 ? w0 : s == 1 ? w1 : w2) >> lane) & 1u;
                    kb = ex ? EMPTY_BITS : kb;
                    if (kb < nvb) { nvb = kb; nj = t * 32 + w; }
                }
                unsigned nmin = __reduce_min_sync(0xffffffffu, nvb);
                unsigned ncj  = (nvb == nmin) ? (unsigned)nj : 0xFFFFFFFFu;
                unsigned nidx = __reduce_min_sync(0xffffffffu, ncj);
                if (lane == w) { v0 = nmin; i0 = (int)nidx; cnt3 = 1; }
            }
        }
    }

    if (lane < KNB) {
        float dv = (rvb == MK_BITS) ? BIGD : sqrtf(__uint_as_float(rvb) + 1e-6f);
        dist_out[lane] = dv;
        idx_out[lane]  = (float)rj;
    }
}

// ---------------------------------------------------------------------------
extern "C" void kernel_launch(void* const* d_in, const int* in_sizes, int n_in,
                              void* d_out, int out_size) {
    const float* coords = (const float*)d_in[0];   // (2,256,12,3) f32
    const int*   mask   = (const int*)d_in[1];     // (2,256) i32
    const float* emb    = (const float*)d_in[2];   // (12,32) f32
    const float* scale  = (const float*)d_in[3];   // (1,1,32) f32
    const float* shift  = (const float*)d_in[4];   // (1,1,32) f32
    float* out = (float*)d_out;

    int smem_bytes = 32 * CPAD * 16;               // 49664 B
    cudaFuncSetAttribute(fused_kernel, cudaFuncAttributeMaxDynamicSharedMemorySize,
                         smem_bytes);
    int nblocks = (NB * NATOM) / ROWS;             // 512
    fused_kernel<<<nblocks, THREADS, smem_bytes>>>(coords, mask, emb, scale, shift, out);
}

// round 6
// speedup vs baseline: 1.1270x; 1.0583x over previous
#include <cuda_runtime.h>
#include <math_constants.h>
#include <cfloat>

// Problem constants (B=2, L=256, A=12, C=32, K=30)
#define NB 2
#define NL 256
#define NA 12
#define NATOM 3072          // NL*NA
#define NC 32
#define KNB 30
#define BIGD 1000000.0f
#define EMPTY_BITS 0xFFFFFFFFu       // list-slot / exclusion sentinel
#define POISON 1.0e18f               // masked-atom coordinate (d2 -> 3e36 exactly)

// Output layout (all float32, concatenated in reference tuple order)
#define O_COORDS 0                       // (B, NATOM, 3)  -> 18432
#define O_MASK   (NB*NATOM*3)            // (B, NATOM)     -> 6144
#define O_ENC    (O_MASK + NB*NATOM)     // (B, NATOM, 32) -> 196608
#define O_DIST   (O_ENC + NB*NATOM*NC)   // (B, NATOM, 30) -> 184320
#define O_IDX    (O_DIST + NB*NATOM*KNB) // (B, NATOM, 30) -> 184320

#define ROWS 12              // rows (queries) per block
#define THREADS (ROWS * 32)  // 384
#define CPAD 97              // per-column padded stride in float4 (conflict-free)
#define NT 96                // candidates per lane/column (3072/32)

// Column-major atom store: s_T[(j&31)*CPAD + (j>>5)] = {x,y,z,mask}

__global__ void __launch_bounds__(THREADS, 4)
fused_kernel(const float* __restrict__ coords,
             const int* __restrict__ mask,
             const float* __restrict__ T,
             const float* __restrict__ scale,
             const float* __restrict__ shift,
             float* __restrict__ out) {
    extern __shared__ float4 s_T[];                  // 32*97 float4 = 49664 B
    __shared__ float s_red[8];

    int tid  = threadIdx.x;
    int warp = tid >> 5;
    int lane = tid & 31;

    int rowBase = blockIdx.x * ROWS;
    int b       = rowBase / NATOM;                   // blocks never straddle batches
    int ibBase  = rowBase - b * NATOM;
    const float* cb = coords + b * NATOM * 3;
    const int*   mb = mask + b * NL;

    // ---- cooperative load of atoms, column-major; poison masked coords ----
    for (int a = tid; a < NATOM; a += THREADS) {
        int m = mb[a / NA];
        float4 v;
        float x = cb[a * 3 + 0], y = cb[a * 3 + 1], z = cb[a * 3 + 2];
        v.x = m ? x : POISON;
        v.y = m ? y : POISON;
        v.z = m ? z : POISON;
        v.w = (float)m;
        s_T[(a & 31) * CPAD + (a >> 5)] = v;
    }

    // ---- nm = sum(mask[b]) : warps 0..7 reduce 32 masks each ----
    if (tid < NL) {
        int s = __reduce_add_sync(0xffffffffu, mb[tid]);
        if (lane == 0) s_red[warp] = (float)s;
    }
    __syncthreads();

    float nm = 0.f;
    #pragma unroll
    for (int i = 0; i < 8; ++i) nm += s_red[i];

    // ---- per-(b,c) graph-norm affine coefficients (closed form) ----
    int c = lane;
    float tv[NA];
    float colsum = 0.f;
    #pragma unroll
    for (int a = 0; a < NA; ++a) { tv[a] = T[a * NC + c]; colsum += tv[a]; }

    float cntA = nm * (float)NA;
    float cnt  = fmaxf(cntA, 1.0f);
    float mean = (nm * colsum) / cnt;

    float ssqm = 0.f;
    #pragma unroll
    for (int a = 0; a < NA; ++a) {
        float d = tv[a] - mean;
        ssqm = fmaf(d, d, ssqm);
    }
    float ssq  = nm * ssqm + ((float)NATOM - cntA) * mean * mean;
    float rstd = rsqrtf(ssq / cnt + 1e-5f);
    float Ac   = rstd * scale[c];
    float Bc   = shift[c] - mean * Ac;

    // ---- small outputs ----
    int row = rowBase + warp;
    int ib  = ibBase + warp;
    float4 q = s_T[(ib & 31) * CPAD + (ib >> 5)];

    {
        int ty = ib % NA;
        float v = (q.w != 0.0f) ? fmaf(tv[ty], Ac, Bc) : 0.0f;
        out[O_ENC + row * NC + c] = v;
    }
    if (tid < ROWS * 3) out[O_COORDS + rowBase * 3 + tid] = coords[rowBase * 3 + tid];
    if (tid < ROWS)     out[O_MASK + rowBase + tid] =
                            s_T[((ibBase + tid) & 31) * CPAD + ((ibBase + tid) >> 5)].w;

    float* dist_out = out + O_DIST + row * KNB;
    float* idx_out  = out + O_IDX  + row * KNB;

    if (q.w == 0.0f) {                        // masked row -> pad outputs
        if (lane < KNB) {
            dist_out[lane] = BIGD;
            idx_out[lane]  = 0.0f;
        }
        return;
    }

    // ---- phase A: branchless per-lane top-2 (key bits, idx) in registers ----
    const float4* myCol = s_T + lane * CPAD;
    unsigned v0 = EMPTY_BITS, v1 = EMPTY_BITS;
    int i0 = 0, i1 = 0;
    #pragma unroll 8
    for (int t = 0; t < NT; ++t) {
        float4 a = myCol[t];
        float dx = q.x - a.x, dy = q.y - a.y, dz = q.z - a.z;
        float d2 = fmaf(dx, dx, fmaf(dy, dy, dz * dz));
        unsigned kb = __float_as_uint(d2);    // d2 >= 0 -> bits order-preserving
        int j = t * 32 + lane;
        bool lt1 = kb < v1;
        bool lt0 = kb < v0;                   // strict < keeps lowest-index tie order
        v1 = lt1 ? (lt0 ? v0 : kb) : v1;
        i1 = lt1 ? (lt0 ? i0 : j ) : i1;
        v0 = lt0 ? kb : v0;
        i0 = lt0 ? j  : i0;
    }

    // ---- extract-min x30 from the 32 lane-heads ----
    unsigned m0 = 0, m1 = 0, m2 = 0;          // exclusion bits of my column
    unsigned rvb = 0; int rj = 0;             // lane p holds pass-p result
    #pragma unroll 1
    for (int p = 0; p < KNB; ++p) {
        unsigned mvb = __reduce_min_sync(0xffffffffu, v0);
        unsigned cj  = (v0 == mvb) ? (unsigned)i0 : 0xFFFFFFFFu;
        unsigned mj  = __reduce_min_sync(0xffffffffu, cj);
        if (lane == p) { rvb = mvb; rj = (int)mj; }

        if (p < KNB - 1) {
            int w  = (int)(mj & 31u);
            int tm = (int)(mj >> 5);
            unsigned bit = 1u << (tm & 31);
            if (lane == w) {                  // owner: record exclusion + pop
                if (tm < 32) m0 |= bit; else if (tm < 64) m1 |= bit; else m2 |= bit;
                v0 = v1; i0 = i1; v1 = EMPTY_BITS;
            }
            bool empty = (lane == w) && (v0 == EMPTY_BITS);
            if (__ballot_sync(0xffffffffu, empty)) {
                // rare: refill owner's head via cooperative rescan of column w
                unsigned w0 = __shfl_sync(0xffffffffu, m0, w);
                unsigned w1 = __shfl_sync(0xffffffffu, m1, w);
                unsigned w2 = __shfl_sync(0xffffffffu, m2, w);
                const float4* col = s_T + w * CPAD;
                unsigned nvb = EMPTY_BITS;
                int nj = 0;
                #pragma unroll
                for (int s = 0; s < 3; ++s) {
                    int t = lane + s * 32;
                    float4 a = col[t];
                    float dx = q.x - a.x, dy = q.y - a.y, dz = q.z - a.z;
                    float d2 = fmaf(dx, dx, fmaf(dy, dy, dz * dz));
                    unsigned kb = __float_as_uint(d2);
                    unsigned ex = ((s == 0 ? w0 : s == 1 ? w1 : w2) >> lane) & 1u;
                    kb = ex ? EMPTY_BITS : kb;
                    if (kb < nvb) { nvb = kb; nj = t * 32 + w; }
                }
                unsigned nmin = __reduce_min_sync(0xffffffffu, nvb);
                unsigned ncj  = (nvb == nmin) ? (unsigned)nj : 0xFFFFFFFFu;
                unsigned nidx = __reduce_min_sync(0xffffffffu, ncj);
                if (lane == w) { v0 = nmin; i0 = (int)nidx; }
            }
        }
    }

    if (lane < KNB) {
        float d2 = __uint_as_float(rvb);
        float dv = (d2 > 1e30f) ? BIGD : sqrtf(d2 + 1e-6f);
        dist_out[lane] = dv;
        idx_out[lane]  = (float)rj;
    }
}

// ---------------------------------------------------------------------------
extern "C" void kernel_launch(void* const* d_in, const int* in_sizes, int n_in,
                              void* d_out, int out_size) {
    const float* coords = (const float*)d_in[0];   // (2,256,12,3) f32
    const int*   mask   = (const int*)d_in[1];     // (2,256) i32
    const float* emb    = (const float*)d_in[2];   // (12,32) f32
    const float* scale  = (const float*)d_in[3];   // (1,1,32) f32
    const float* shift  = (const float*)d_in[4];   // (1,1,32) f32
    float* out = (float*)d_out;

    int smem_bytes = 32 * CPAD * 16;               // 49664 B
    cudaFuncSetAttribute(fused_kernel, cudaFuncAttributeMaxDynamicSharedMemorySize,
                         smem_bytes);
    int nblocks = (NB * NATOM) / ROWS;             // 512
    fused_kernel<<<nblocks, THREADS, smem_bytes>>>(coords, mask, emb, scale, shift, out);
}

// round 7
// speedup vs baseline: 1.1846x; 1.0512x over previous
#include <cuda_runtime.h>
#include <math_constants.h>
#include <cfloat>

// Problem constants (B=2, L=256, A=12, C=32, K=30)
#define NB 2
#define NL 256
#define NA 12
#define NATOM 3072          // NL*NA
#define NC 32
#define KNB 30
#define BIGD 1000000.0f
#define EMPTY_BITS 0xFFFFFFFFu       // list-slot / exclusion sentinel
#define POISON 1.0e18f               // masked-atom coordinate (d2 -> 3e36 exactly)

// Output layout (all float32, concatenated in reference tuple order)
#define O_COORDS 0                       // (B, NATOM, 3)  -> 18432
#define O_MASK   (NB*NATOM*3)            // (B, NATOM)     -> 6144
#define O_ENC    (O_MASK + NB*NATOM)     // (B, NATOM, 32) -> 196608
#define O_DIST   (O_ENC + NB*NATOM*NC)   // (B, NATOM, 30) -> 184320
#define O_IDX    (O_DIST + NB*NATOM*KNB) // (B, NATOM, 30) -> 184320

#define ROWSK 4              // rows (queries) per block
#define THR (ROWSK * 32)     // 128
#define NT 96                // candidates per lane/column (3072/32)

__device__ float4 g_atoms[NB * NATOM];   // poisoned {x,y,z,mask}, 98 KB
__device__ float  g_A[NB * NC];          // rstd * scale
__device__ float  g_B[NB * NC];          // shift - mean * rstd * scale

// ---------------------------------------------------------------------------
// Prep: block 0 computes graph-norm coefs; all blocks poison the atom table.
// ---------------------------------------------------------------------------
#define PREP_BLOCKS 25
__global__ void prep_kernel(const float* __restrict__ coords,
                            const int* __restrict__ mask,
                            const float* __restrict__ T,
                            const float* __restrict__ scale,
                            const float* __restrict__ shift) {
    int tid = threadIdx.x;     // 256

    if (blockIdx.x == 0) {
        __shared__ float sred[NB][8];
        int warp = tid >> 5, lane = tid & 31;
        int s0 = __reduce_add_sync(0xffffffffu, mask[tid]);
        int s1 = __reduce_add_sync(0xffffffffu, mask[NL + tid]);
        if (lane == 0) { sred[0][warp] = (float)s0; sred[1][warp] = (float)s1; }
        __syncthreads();
        if (tid < NB * NC) {
            int b = tid >> 5, c = tid & 31;
            float nm = 0.f;
            #pragma unroll
            for (int i = 0; i < 8; ++i) nm += sred[b][i];
            float colsum = 0.f, tv[NA];
            #pragma unroll
            for (int a = 0; a < NA; ++a) { tv[a] = T[a * NC + c]; colsum += tv[a]; }
            float cntA = nm * (float)NA;
            float cnt  = fmaxf(cntA, 1.0f);
            float mean = (nm * colsum) / cnt;
            float ssqm = 0.f;
            #pragma unroll
            for (int a = 0; a < NA; ++a) {
                float d = tv[a] - mean;
                ssqm = fmaf(d, d, ssqm);
            }
            float ssq  = nm * ssqm + ((float)NATOM - cntA) * mean * mean;
            float rstd = rsqrtf(ssq / cnt + 1e-5f);
            float Ac   = rstd * scale[c];
            g_A[tid] = Ac;
            g_B[tid] = shift[c] - mean * Ac;
        }
    }

    // poison atoms (all blocks, grid-stride)
    for (int a = blockIdx.x * 256 + tid; a < NB * NATOM; a += PREP_BLOCKS * 256) {
        int b = a / NATOM;
        int j = a - b * NATOM;
        int m = mask[b * NL + j / NA];
        float4 v;
        float x = coords[a * 3 + 0], y = coords[a * 3 + 1], z = coords[a * 3 + 2];
        v.x = m ? x : POISON;
        v.y = m ? y : POISON;
        v.z = m ? z : POISON;
        v.w = (float)m;
        g_atoms[a] = v;
    }
}

// ---------------------------------------------------------------------------
// KNN: warp-per-row, register-only top-2 lists + 2-redux extraction.
// No shared memory, no block barriers.
// ---------------------------------------------------------------------------
__global__ void __launch_bounds__(THR, 12)
knn_kernel(const float* __restrict__ coords,
           const float* __restrict__ T,
           float* __restrict__ out) {
    int tid  = threadIdx.x;
    int warp = tid >> 5;
    int lane = tid & 31;

    int rowBase = blockIdx.x * ROWSK;
    int b       = rowBase / NATOM;                   // blocks never straddle batches
    int row     = rowBase + warp;
    int ib      = row - b * NATOM;
    const float4* At = g_atoms + b * NATOM;

    float4 q = __ldg(&At[ib]);

    // ---- small outputs (encode / coords / mask) ----
    {
        int ty = ib % NA;
        float v = (q.w != 0.0f)
                    ? fmaf(__ldg(&T[ty * NC + lane]), g_A[b * NC + lane], g_B[b * NC + lane])
                    : 0.0f;
        out[O_ENC + row * NC + lane] = v;
    }
    if (tid < ROWSK * 3) out[O_COORDS + rowBase * 3 + tid] = coords[rowBase * 3 + tid];
    if (tid < ROWSK)     out[O_MASK + rowBase + tid] = __ldg(&At[rowBase - b * NATOM + tid].w);

    float* dist_out = out + O_DIST + row * KNB;
    float* idx_out  = out + O_IDX  + row * KNB;

    if (q.w == 0.0f) {                        // masked row -> pad outputs
        if (lane < KNB) {
            dist_out[lane] = BIGD;
            idx_out[lane]  = 0.0f;
        }
        return;
    }

    // ---- phase A: branchless per-lane top-2 (key bits, idx) in registers ----
    unsigned v0 = EMPTY_BITS, v1 = EMPTY_BITS;
    int i0 = 0, i1 = 0;
    #pragma unroll 8
    for (int t = 0; t < NT; ++t) {
        float4 a = __ldg(&At[t * 32 + lane]);
        float dx = q.x - a.x, dy = q.y - a.y, dz = q.z - a.z;
        float d2 = fmaf(dx, dx, fmaf(dy, dy, dz * dz));
        unsigned kb = __float_as_uint(d2);    // d2 >= 0 -> bits order-preserving
        int j = t * 32 + lane;
        bool lt1 = kb < v1;
        bool lt0 = kb < v0;                   // strict < keeps lowest-index tie order
        v1 = lt1 ? (lt0 ? v0 : kb) : v1;
        i1 = lt1 ? (lt0 ? i0 : j ) : i1;
        v0 = lt0 ? kb : v0;
        i0 = lt0 ? j  : i0;
    }

    // ---- extract-min x30 from the 32 lane-heads ----
    unsigned m0 = 0, m1 = 0, m2 = 0;          // exclusion bits of my column
    unsigned rvb = 0; int rj = 0;             // lane p holds pass-p result
    #pragma unroll 1
    for (int p = 0; p < KNB; ++p) {
        unsigned mvb = __reduce_min_sync(0xffffffffu, v0);
        unsigned cj  = (v0 == mvb) ? (unsigned)i0 : 0xFFFFFFFFu;
        unsigned mj  = __reduce_min_sync(0xffffffffu, cj);
        if (lane == p) { rvb = mvb; rj = (int)mj; }

        if (p < KNB - 1) {
            int w  = (int)(mj & 31u);
            int tm = (int)(mj >> 5);
            unsigned bit = 1u << (tm & 31);
            if (lane == w) {                  // owner: record exclusion + pop
                if (tm < 32) m0 |= bit; else if (tm < 64) m1 |= bit; else m2 |= bit;
                v0 = v1; i0 = i1; v1 = EMPTY_BITS;
            }
            bool empty = (lane == w) && (v0 == EMPTY_BITS);
            if (__ballot_sync(0xffffffffu, empty)) {
                // rare: refill owner's head via cooperative rescan of column w
                unsigned w0 = __shfl_sync(0xffffffffu, m0, w);
                unsigned w1 = __shfl_sync(0xffffffffu, m1, w);
                unsigned w2 = __shfl_sync(0xffffffffu, m2, w);
                unsigned nvb = EMPTY_BITS;
                int nj = 0;
                #pragma unroll
                for (int s = 0; s < 3; ++s) {
                    int t = lane + s * 32;
                    float4 a = __ldg(&At[t * 32 + w]);
                    float dx = q.x - a.x, dy = q.y - a.y, dz = q.z - a.z;
                    float d2 = fmaf(dx, dx, fmaf(dy, dy, dz * dz));
                    unsigned kb = __float_as_uint(d2);
                    unsigned ex = ((s == 0 ? w0 : s == 1 ? w1 : w2) >> lane) & 1u;
                    kb = ex ? EMPTY_BITS : kb;
                    if (kb < nvb) { nvb = kb; nj = t * 32 + w; }
                }
                unsigned nmin = __reduce_min_sync(0xffffffffu, nvb);
                unsigned ncj  = (nvb == nmin) ? (unsigned)nj : 0xFFFFFFFFu;
                unsigned nidx = __reduce_min_sync(0xffffffffu, ncj);
                if (lane == w) { v0 = nmin; i0 = (int)nidx; }
            }
        }
    }

    if (lane < KNB) {
        float d2 = __uint_as_float(rvb);
        float dv = (d2 > 1e30f) ? BIGD : sqrtf(d2 + 1e-6f);
        dist_out[lane] = dv;
        idx_out[lane]  = (float)rj;
    }
}

// ---------------------------------------------------------------------------
extern "C" void kernel_launch(void* const* d_in, const int* in_sizes, int n_in,
                              void* d_out, int out_size) {
    const float* coords = (const float*)d_in[0];   // (2,256,12,3) f32
    const int*   mask   = (const int*)d_in[1];     // (2,256) i32
    const float* emb    = (const float*)d_in[2];   // (12,32) f32
    const float* scale  = (const float*)d_in[3];   // (1,1,32) f32
    const float* shift  = (const float*)d_in[4];   // (1,1,32) f32
    float* out = (float*)d_out;

    prep_kernel<<<PREP_BLOCKS, 256>>>(coords, mask, emb, scale, shift);

    int nblocks = (NB * NATOM) / ROWSK;            // 1536
    knn_kernel<<<nblocks, THR>>>(coords, emb, out);
}

// round 8
// speedup vs baseline: 1.6573x; 1.3990x over previous
#include <cuda_runtime.h>
#include <math_constants.h>
#include <cfloat>

// Problem constants (B=2, L=256, A=12, C=32, K=30)
#define NB 2
#define NL 256
#define NA 12
#define NATOM 3072          // NL*NA
#define NC 32
#define KNB 30
#define BIGD 1000000.0f
#define EMPTY_BITS 0xFFFFFFFFu
#define POISON 1.0e18f               // masked-atom coordinate (d2 -> 3e36 exactly)

// Output layout (all float32, concatenated in reference tuple order)
#define O_COORDS 0                       // (B, NATOM, 3)  -> 18432
#define O_MASK   (NB*NATOM*3)            // (B, NATOM)     -> 6144
#define O_ENC    (O_MASK + NB*NATOM)     // (B, NATOM, 32) -> 196608
#define O_DIST   (O_ENC + NB*NATOM*NC)   // (B, NATOM, 30) -> 184320
#define O_IDX    (O_DIST + NB*NATOM*KNB) // (B, NATOM, 30) -> 184320

#define WARPS 6              // rows (queries) per block
#define THR (WARPS * 32)     // 192
#define TPAD 97              // padded key-slice stride (32*97 floats per warp)
#define NT 96                // candidates per lane/column (3072/32)

__device__ float4 g_atoms[NB * NATOM];   // poisoned {x,y,z,mask}, 98 KB
__device__ float  g_A[NB * NC];          // rstd * scale
__device__ float  g_B[NB * NC];          // shift - mean * rstd * scale

// ---------------------------------------------------------------------------
// Prep: block 0 computes graph-norm coefs; all blocks poison the atom table.
// ---------------------------------------------------------------------------
#define PREP_BLOCKS 25
__global__ void prep_kernel(const float* __restrict__ coords,
                            const int* __restrict__ mask,
                            const float* __restrict__ T,
                            const float* __restrict__ scale,
                            const float* __restrict__ shift) {
    int tid = threadIdx.x;     // 256

    if (blockIdx.x == 0) {
        __shared__ float sred[NB][8];
        int warp = tid >> 5, lane = tid & 31;
        int s0 = __reduce_add_sync(0xffffffffu, mask[tid]);
        int s1 = __reduce_add_sync(0xffffffffu, mask[NL + tid]);
        if (lane == 0) { sred[0][warp] = (float)s0; sred[1][warp] = (float)s1; }
        __syncthreads();
        if (tid < NB * NC) {
            int b = tid >> 5, c = tid & 31;
            float nm = 0.f;
            #pragma unroll
            for (int i = 0; i < 8; ++i) nm += sred[b][i];
            float colsum = 0.f, tv[NA];
            #pragma unroll
            for (int a = 0; a < NA; ++a) { tv[a] = T[a * NC + c]; colsum += tv[a]; }
            float cntA = nm * (float)NA;
            float cnt  = fmaxf(cntA, 1.0f);
            float mean = (nm * colsum) / cnt;
            float ssqm = 0.f;
            #pragma unroll
            for (int a = 0; a < NA; ++a) {
                float d = tv[a] - mean;
                ssqm = fmaf(d, d, ssqm);
            }
            float ssq  = nm * ssqm + ((float)NATOM - cntA) * mean * mean;
            float rstd = rsqrtf(ssq / cnt + 1e-5f);
            float Ac   = rstd * scale[c];
            g_A[tid] = Ac;
            g_B[tid] = shift[c] - mean * Ac;
        }
    }

    // poison atoms (all blocks, grid-stride)
    for (int a = blockIdx.x * 256 + tid; a < NB * NATOM; a += PREP_BLOCKS * 256) {
        int b = a / NATOM;
        int j = a - b * NATOM;
        int m = mask[b * NL + j / NA];
        float4 v;
        float x = coords[a * 3 + 0], y = coords[a * 3 + 1], z = coords[a * 3 + 2];
        v.x = m ? x : POISON;
        v.y = m ? y : POISON;
        v.z = m ? z : POISON;
        v.w = (float)m;
        g_atoms[a] = v;
    }
}

// ---------------------------------------------------------------------------
// KNN: warp-per-row. Phase A reads global atoms (coalesced), caches keys in
// smem. Selection = extract-min x30 with unconditional 3-LDS rescan per pass
// (R2 engine). smem 74.5 KB -> 3 blocks/SM (18 warps/SM).
// ---------------------------------------------------------------------------
__global__ void __launch_bounds__(THR, 3)
knn_kernel(const float* __restrict__ coords,
           const float* __restrict__ T,
           float* __restrict__ out) {
    extern __shared__ float s_d2[];                  // WARPS*32*97 = 74496 B

    int tid  = threadIdx.x;
    int warp = tid >> 5;
    int lane = tid & 31;

    int rowBase = blockIdx.x * WARPS;
    int b       = rowBase / NATOM;                   // blocks never straddle batches
    int row     = rowBase + warp;
    int ib      = row - b * NATOM;
    const float4* At = g_atoms + b * NATOM;

    float4 q = __ldg(&At[ib]);

    // ---- small outputs (encode / coords / mask) ----
    {
        int ty = ib % NA;
        float v = (q.w != 0.0f)
                    ? fmaf(__ldg(&T[ty * NC + lane]), g_A[b * NC + lane], g_B[b * NC + lane])
                    : 0.0f;
        out[O_ENC + row * NC + lane] = v;
    }
    if (tid < WARPS * 3) out[O_COORDS + rowBase * 3 + tid] = coords[rowBase * 3 + tid];
    if (tid < WARPS)     out[O_MASK + rowBase + tid] = __ldg(&At[rowBase - b * NATOM + tid].w);

    float* dist_out = out + O_DIST + row * KNB;
    float* idx_out  = out + O_IDX  + row * KNB;

    if (q.w == 0.0f) {                        // masked row -> pad outputs
        if (lane < KNB) {
            dist_out[lane] = BIGD;
            idx_out[lane]  = 0.0f;
        }
        return;
    }

    float* my = s_d2 + warp * (32 * TPAD);

    // ---- phase A: compute keys from global atoms, cache in smem,
    //      track per-lane running (min, idx) ----
    unsigned bvb = EMPTY_BITS;
    int bj = 0;
    #pragma unroll 8
    for (int t = 0; t < NT; ++t) {
        float4 a = __ldg(&At[t * 32 + lane]);
        float dx = q.x - a.x, dy = q.y - a.y, dz = q.z - a.z;
        float d2 = fmaf(dx, dx, fmaf(dy, dy, dz * dz));
        my[lane * TPAD + t] = d2;
        unsigned kb = __float_as_uint(d2);    // d2 >= 0 -> bits order-preserving
        if (kb < bvb) { bvb = kb; bj = t * 32 + lane; }  // t asc -> lowest j ties
    }
    __syncwarp();

    // ---- extract-min x30 with unconditional cooperative rescan ----
    unsigned rvb = 0; int rj = 0;             // lane p holds pass-p result
    #pragma unroll 1
    for (int p = 0; p < KNB; ++p) {
        unsigned mvb = __reduce_min_sync(0xffffffffu, bvb);
        unsigned cj  = (bvb == mvb) ? (unsigned)bj : 0xFFFFFFFFu;
        unsigned mj  = __reduce_min_sync(0xffffffffu, cj);
        if (lane == p) { rvb = mvb; rj = (int)mj; }

        if (p < KNB - 1) {
            int w  = (int)(mj & 31u);
            int tm = (int)(mj >> 5);
            // owner invalidates extracted slot; all lanes rescan column w
            unsigned nvb = EMPTY_BITS;
            int nj = 0;
            #pragma unroll
            for (int s = 0; s < 3; ++s) {
                int t = lane + s * 32;
                float v = my[w * TPAD + t];
                unsigned vb = __float_as_uint(v);
                if (t == tm) { my[w * TPAD + t] = CUDART_INF_F; vb = EMPTY_BITS; }
                if (vb < nvb) { nvb = vb; nj = t * 32 + w; }
            }
            __syncwarp();
            unsigned nmin = __reduce_min_sync(0xffffffffu, nvb);
            unsigned ncj  = (nvb == nmin) ? (unsigned)nj : 0xFFFFFFFFu;
            unsigned nidx = __reduce_min_sync(0xffffffffu, ncj);
            if (lane == w) { bvb = nmin; bj = (int)nidx; }
        }
    }

    if (lane < KNB) {
        float d2 = __uint_as_float(rvb);
        float dv = (d2 > 1e30f) ? BIGD : sqrtf(d2 + 1e-6f);
        dist_out[lane] = dv;
        idx_out[lane]  = (float)rj;
    }
}

// ---------------------------------------------------------------------------
extern "C" void kernel_launch(void* const* d_in, const int* in_sizes, int n_in,
                              void* d_out, int out_size) {
    const float* coords = (const float*)d_in[0];   // (2,256,12,3) f32
    const int*   mask   = (const int*)d_in[1];     // (2,256) i32
    const float* emb    = (const float*)d_in[2];   // (12,32) f32
    const float* scale  = (const float*)d_in[3];   // (1,1,32) f32
    const float* shift  = (const float*)d_in[4];   // (1,1,32) f32
    float* out = (float*)d_out;

    prep_kernel<<<PREP_BLOCKS, 256>>>(coords, mask, emb, scale, shift);

    int smem_bytes = WARPS * 32 * TPAD * 4;        // 74496
    cudaFuncSetAttribute(knn_kernel, cudaFuncAttributeMaxDynamicSharedMemorySize,
                         smem_bytes);
    int nblocks = (NB * NATOM) / WARPS;            // 1024
    knn_kernel<<<nblocks, THR, smem_bytes>>>(coords, emb, out);
}